// round 2
// baseline (speedup 1.0000x reference)
#include <cuda_runtime.h>
#include <stdint.h>

// GreedyGroupedRouter: SEQ=524288 tokens, 256 experts, 8 groups of 32, top-1/group.
// d_out layout (float32): rw[SEQ*256] | tw[SEQ*8] | tids[SEQ*8] | hist[256]

#define SEQ     524288
#define NE      256
#define NG      8
#define TOPK    8
#define L2E     1.4426950408889634f

__global__ void zero_hist_kernel(float* hist) {
    hist[threadIdx.x] = 0.0f;
}

// float -> order-preserving uint (and back) for REDUX-based max
__device__ __forceinline__ unsigned f2ord(float f) {
    unsigned u = __float_as_uint(f);
    return u ^ (0x80000000u | (unsigned)((int)u >> 31));
}
__device__ __forceinline__ float ord2f(unsigned k) {
    unsigned u = (k & 0x80000000u) ? (k ^ 0x80000000u) : ~k;
    return __uint_as_float(u);
}

__global__ void __launch_bounds__(256)
router_kernel(const float* __restrict__ logits,
              float* __restrict__ rw,     // [SEQ, 256]
              float* __restrict__ tw,     // [SEQ, 8]
              float* __restrict__ tids,   // [SEQ, 8]
              float* __restrict__ hist)   // [256]
{
    __shared__ unsigned int shist[NE];
    for (int i = threadIdx.x; i < NE; i += blockDim.x) shist[i] = 0u;
    __syncthreads();

    const int lane   = threadIdx.x & 31;
    const int gwarp  = blockIdx.x * (blockDim.x >> 5) + (threadIdx.x >> 5);
    const int nwarps = gridDim.x * (blockDim.x >> 5);
    const int seg    = lane >> 3;          // 0..3  (8-lane segment id)
    const int sub    = (lane & 7) * 4;     // in-group index base of this lane's quad

    for (int row = gwarp; row < SEQ; row += nwarps) {
        const float4* lp4 = (const float4*)(logits + (size_t)row * NE);

        // chunk a = elements [4l..4l+3]      -> group (l>>3)
        // chunk b = elements [128+4l..4l+3]  -> group 4+(l>>3)
        float4 a = lp4[lane];
        float4 b = lp4[lane + 32];

        // ---- row max (one REDUX via order-preserving uint) ----
        float lm = fmaxf(fmaxf(fmaxf(a.x, a.y), fmaxf(a.z, a.w)),
                         fmaxf(fmaxf(b.x, b.y), fmaxf(b.z, b.w)));
        float m = ord2f(__reduce_max_sync(0xffffffffu, f2ord(lm)));
        float nm = -m * L2E;

        // ---- exp + row sum ----
        float4 ea, eb;
        ea.x = exp2f(fmaf(a.x, L2E, nm)); ea.y = exp2f(fmaf(a.y, L2E, nm));
        ea.z = exp2f(fmaf(a.z, L2E, nm)); ea.w = exp2f(fmaf(a.w, L2E, nm));
        eb.x = exp2f(fmaf(b.x, L2E, nm)); eb.y = exp2f(fmaf(b.y, L2E, nm));
        eb.z = exp2f(fmaf(b.z, L2E, nm)); eb.w = exp2f(fmaf(b.w, L2E, nm));
        float s = ((ea.x + ea.y) + (ea.z + ea.w)) + ((eb.x + eb.y) + (eb.z + eb.w));
        #pragma unroll
        for (int o = 16; o > 0; o >>= 1)
            s += __shfl_xor_sync(0xffffffffu, s, o);
        const float inv = 1.0f / s;

        // ---- softmax weights + streaming vector store ----
        float4 wa, wb;
        wa.x = ea.x * inv; wa.y = ea.y * inv; wa.z = ea.z * inv; wa.w = ea.w * inv;
        wb.x = eb.x * inv; wb.y = eb.y * inv; wb.z = eb.z * inv; wb.w = eb.w * inv;
        float4* rp4 = (float4*)(rw + (size_t)row * NE);
        rp4[lane]      = wa;
        rp4[lane + 32] = wb;

        // ---- per-group argmax (exact lowest-index tie-break) ----
        // local argmax over 4 (strict > keeps lowest index)
        float va = wa.x; int ia = sub;
        if (wa.y > va) { va = wa.y; ia = sub + 1; }
        if (wa.z > va) { va = wa.z; ia = sub + 2; }
        if (wa.w > va) { va = wa.w; ia = sub + 3; }
        float vb = wb.x; int ib = sub;
        if (wb.y > vb) { vb = wb.y; ib = sub + 1; }
        if (wb.z > vb) { vb = wb.z; ib = sub + 2; }
        if (wb.w > vb) { vb = wb.w; ib = sub + 3; }

        // 8-lane segment reduce (xor 1,2,4); ia/ib are in-group indices 0..31
        #pragma unroll
        for (int o = 1; o <= 4; o <<= 1) {
            float ova = __shfl_xor_sync(0xffffffffu, va, o);
            int   oia = __shfl_xor_sync(0xffffffffu, ia, o);
            if (ova > va || (ova == va && oia < ia)) { va = ova; ia = oia; }
            float ovb = __shfl_xor_sync(0xffffffffu, vb, o);
            int   oib = __shfl_xor_sync(0xffffffffu, ib, o);
            if (ovb > vb || (ovb == vb && oib < ib)) { vb = ovb; ib = oib; }
        }
        // expert ids of the two group winners this segment computed
        int eida = (seg << 5) + ia;            // group seg
        int eidb = ((seg + 4) << 5) + ib;      // group seg+4

        // ---- gather: lane L takes group g = L&7 (src segment = g&3) ----
        int g   = lane & 7;
        int src = (g & 3) << 3;                // leader lane of segment g&3
        float gva = __shfl_sync(0xffffffffu, va, src);
        float gvb = __shfl_sync(0xffffffffu, vb, src);
        int   gia = __shfl_sync(0xffffffffu, eida, src);
        int   gib = __shfl_sync(0xffffffffu, eidb, src);
        float myw  = (g < 4) ? gva : gvb;
        int   myid = (g < 4) ? gia : gib;

        // sum of the 8 group winners (each xor-octet holds all 8 groups once)
        float sw = myw;
        #pragma unroll
        for (int o = 1; o <= 4; o <<= 1)
            sw += __shfl_xor_sync(0xffffffffu, sw, o);
        const float invsw = 1.0f / (sw + 1e-20f);

        if (lane < TOPK) {
            tw[(size_t)row * TOPK + lane]   = myw * invsw;
            tids[(size_t)row * TOPK + lane] = (float)myid;
            atomicAdd(&shist[myid], 1u);
        }
    }

    __syncthreads();
    for (int i = threadIdx.x; i < NE; i += blockDim.x) {
        unsigned c = shist[i];
        if (c) atomicAdd(&hist[i], (float)c);
    }
}

extern "C" void kernel_launch(void* const* d_in, const int* in_sizes, int n_in,
                              void* d_out, int out_size) {
    const float* logits = (const float*)d_in[0];
    float* out  = (float*)d_out;
    float* rw   = out;
    float* tw   = rw   + (size_t)SEQ * NE;
    float* tids = tw   + (size_t)SEQ * TOPK;
    float* hist = tids + (size_t)SEQ * TOPK;

    zero_hist_kernel<<<1, NE>>>(hist);
    // 152 SMs x 8 blocks, 256 threads: 9728 warps, ~54 rows/warp grid-stride.
    router_kernel<<<1216, 256>>>(logits, rw, tw, tids, hist);
}